// round 1
// baseline (speedup 1.0000x reference)
#include <cuda_runtime.h>
#include <math.h>

// Problem dims
constexpr int Bc = 4, Sc = 2048, Dc = 2048, Hc = 16, HDc = 128;
constexpr int Mc = Bc * Sc;  // 8192 rows for all GEMMs

// Scratch (module-static device memory: allowed; no runtime allocation)
__device__ float g_Q[Bc * Hc * Sc * HDc];  // [B,H,S,HD]
__device__ float g_K[Bc * Hc * Sc * HDc];  // [B,H,S,HD]
__device__ float g_V[Bc * Hc * Sc * HDc];  // [B,H,S,HD]
__device__ float g_O[Bc * Sc * Dc];        // [B,S,D]

// ---------------------------------------------------------------------------
// GEMM: C[M,N] = A[M,K] * W[N,K]^T   (both K-contiguous row-major)
// MODE 0: plain row-major output [M,N]
// MODE 1: output scattered to [B,H,S,HD]
// MODE 2: MODE 1 + RoPE applied per (s, head-dim pair)
// Tiles: 128x128x16, 256 threads, 8x8 microtile per thread.
// ---------------------------------------------------------------------------
template <int MODE>
__global__ void __launch_bounds__(256, 2)
gemm_nt(const float* __restrict__ A, const float* __restrict__ W,
        float* __restrict__ out, const int* __restrict__ pos)
{
    constexpr int Kd = Dc;
    constexpr int Nd = Dc;
    __shared__ float As[16][132];  // [k][m], padded stride
    __shared__ float Bs[16][132];  // [k][n]

    const int tid = threadIdx.x;
    const int bm = blockIdx.y * 128;
    const int bn = blockIdx.x * 128;
    const int tx = tid & 15;      // n-tile position
    const int ty = tid >> 4;      // m-tile position

    // global->smem load assignment: 512 float4 per tile per operand
    const int r0 = tid >> 2;             // 0..63
    const int q0 = (tid & 3) * 4;        // k offset 0,4,8,12
    const float* Ap = A + (size_t)(bm + r0) * Kd + q0;
    const float* Wp = W + (size_t)(bn + r0) * Kd + q0;
    const size_t rstep = (size_t)64 * Kd;

    float acc[8][8];
#pragma unroll
    for (int i = 0; i < 8; i++)
#pragma unroll
        for (int j = 0; j < 8; j++) acc[i][j] = 0.0f;

    for (int kt = 0; kt < Kd; kt += 16) {
        float4 a0 = *(const float4*)(Ap + kt);
        float4 a1 = *(const float4*)(Ap + kt + rstep);
        float4 b0 = *(const float4*)(Wp + kt);
        float4 b1 = *(const float4*)(Wp + kt + rstep);

        As[q0 + 0][r0] = a0.x; As[q0 + 1][r0] = a0.y;
        As[q0 + 2][r0] = a0.z; As[q0 + 3][r0] = a0.w;
        As[q0 + 0][r0 + 64] = a1.x; As[q0 + 1][r0 + 64] = a1.y;
        As[q0 + 2][r0 + 64] = a1.z; As[q0 + 3][r0 + 64] = a1.w;
        Bs[q0 + 0][r0] = b0.x; Bs[q0 + 1][r0] = b0.y;
        Bs[q0 + 2][r0] = b0.z; Bs[q0 + 3][r0] = b0.w;
        Bs[q0 + 0][r0 + 64] = b1.x; Bs[q0 + 1][r0 + 64] = b1.y;
        Bs[q0 + 2][r0 + 64] = b1.z; Bs[q0 + 3][r0 + 64] = b1.w;
        __syncthreads();

#pragma unroll
        for (int kk = 0; kk < 16; kk++) {
            float av[8], bv[8];
            *(float4*)(av)     = *(const float4*)(&As[kk][ty * 8]);
            *(float4*)(av + 4) = *(const float4*)(&As[kk][ty * 8 + 4]);
            *(float4*)(bv)     = *(const float4*)(&Bs[kk][tx * 8]);
            *(float4*)(bv + 4) = *(const float4*)(&Bs[kk][tx * 8 + 4]);
#pragma unroll
            for (int i = 0; i < 8; i++)
#pragma unroll
                for (int j = 0; j < 8; j++)
                    acc[i][j] = fmaf(av[i], bv[j], acc[i][j]);
        }
        __syncthreads();
    }

    if (MODE == 0) {
#pragma unroll
        for (int i = 0; i < 8; i++) {
            float* op = out + (size_t)(bm + ty * 8 + i) * Nd + bn + tx * 8;
            *(float4*)(op)     = make_float4(acc[i][0], acc[i][1], acc[i][2], acc[i][3]);
            *(float4*)(op + 4) = make_float4(acc[i][4], acc[i][5], acc[i][6], acc[i][7]);
        }
    } else {
        const int n0 = bn + tx * 8;     // 8 consecutive output dims, within one head
        const int h = n0 >> 7;          // n0 / HD
        const int hd0 = n0 & 127;       // even; pairs (hd0+2j, hd0+2j+1)
        float invf[4];
        if (MODE == 2) {
#pragma unroll
            for (int j2 = 0; j2 < 4; j2++) {
                // inv_freq = 10000^(-(hd)/128), hd = even index
                double e = -(double)(hd0 + 2 * j2) * (13.287712379549449 / 128.0);
                invf[j2] = (float)exp2(e);
            }
        }
#pragma unroll
        for (int i = 0; i < 8; i++) {
            const int m = bm + ty * 8 + i;
            const int b = m >> 11;           // m / S
            const int s = m & 2047;          // m % S
            float* op = out + (((size_t)b * Hc + h) * Sc + s) * HDc + hd0;
            float r[8];
            if (MODE == 2) {
                const float p = (float)pos[s];
#pragma unroll
                for (int j2 = 0; j2 < 4; j2++) {
                    float ang = p * invf[j2];
                    float sn, cs;
                    sincosf(ang, &sn, &cs);
                    float x1 = acc[i][2 * j2];
                    float x2 = acc[i][2 * j2 + 1];
                    r[2 * j2]     = x1 * cs - x2 * sn;
                    r[2 * j2 + 1] = x1 * sn + x2 * cs;
                }
            } else {
#pragma unroll
                for (int j = 0; j < 8; j++) r[j] = acc[i][j];
            }
            *(float4*)(op)     = make_float4(r[0], r[1], r[2], r[3]);
            *(float4*)(op + 4) = make_float4(r[4], r[5], r[6], r[7]);
        }
    }
}

// ---------------------------------------------------------------------------
// Flash attention (causal), fp32. One CTA = one (b,h) x 64 query rows.
// K/V tiles of 64 keys staged in smem; online softmax; P staged in smem.
// Thread layout: rg = tid/16 owns rows {rg, rg+16, rg+32, rg+48};
//                cg = tid%16 owns keys {cg, cg+16, cg+32, cg+48} (score phase)
//                and output cols [cg*8, cg*8+8) (PV phase).
// ---------------------------------------------------------------------------
__global__ void __launch_bounds__(256, 1)
attn_kernel(const float* __restrict__ Q, const float* __restrict__ K,
            const float* __restrict__ V, float* __restrict__ O)
{
    extern __shared__ float sm[];
    float* Qs = sm;                    // 64 x 132
    float* Ks = Qs + 64 * 132;         // 64 x 132
    float* Vs = Ks + 64 * 132;         // 64 x 132
    float* Ps = Vs + 64 * 132;         // 64 x 65

    const int tid = threadIdx.x;
    const int qb = blockIdx.x;         // query block: rows [qb*64, qb*64+64)
    const int bh = blockIdx.y;         // b*H + h
    const int q0 = qb * 64;
    const size_t hoff = (size_t)bh * Sc * HDc;
    const float scale = 0.08838834764831845f;  // 1/sqrt(128)

    // Load Q tile (pre-scaled)
    const float* Qg = Q + hoff + (size_t)q0 * HDc;
    for (int i = tid; i < 64 * 32; i += 256) {
        int r = i >> 5, c = (i & 31) * 4;
        float4 v = *(const float4*)(Qg + (size_t)r * HDc + c);
        v.x *= scale; v.y *= scale; v.z *= scale; v.w *= scale;
        *(float4*)&Qs[r * 132 + c] = v;
    }

    const int rg = tid >> 4;
    const int cg = tid & 15;
    float m_i[4], l_i[4], accO[4][8];
#pragma unroll
    for (int i = 0; i < 4; i++) {
        m_i[i] = -1e30f;
        l_i[i] = 0.0f;
#pragma unroll
        for (int j = 0; j < 8; j++) accO[i][j] = 0.0f;
    }
    __syncthreads();

    for (int kb = 0; kb <= qb; kb++) {
        const float* Kg = K + hoff + (size_t)kb * 64 * HDc;
        const float* Vg = V + hoff + (size_t)kb * 64 * HDc;
        for (int i = tid; i < 64 * 32; i += 256) {
            int r = i >> 5, c = (i & 31) * 4;
            *(float4*)&Ks[r * 132 + c] = *(const float4*)(Kg + (size_t)r * HDc + c);
            *(float4*)&Vs[r * 132 + c] = *(const float4*)(Vg + (size_t)r * HDc + c);
        }
        __syncthreads();

        // Scores: s[i][j] = Qrow(rg+16i) . Krow(cg+16j)
        float s[4][4];
#pragma unroll
        for (int i = 0; i < 4; i++)
#pragma unroll
            for (int j = 0; j < 4; j++) s[i][j] = 0.0f;

        for (int d = 0; d < 128; d += 4) {
            float4 qv[4], kv[4];
#pragma unroll
            for (int i = 0; i < 4; i++)
                qv[i] = *(const float4*)&Qs[(rg + 16 * i) * 132 + d];
#pragma unroll
            for (int j = 0; j < 4; j++)
                kv[j] = *(const float4*)&Ks[(cg + 16 * j) * 132 + d];
#pragma unroll
            for (int i = 0; i < 4; i++)
#pragma unroll
                for (int j = 0; j < 4; j++) {
                    s[i][j] = fmaf(qv[i].x, kv[j].x, s[i][j]);
                    s[i][j] = fmaf(qv[i].y, kv[j].y, s[i][j]);
                    s[i][j] = fmaf(qv[i].z, kv[j].z, s[i][j]);
                    s[i][j] = fmaf(qv[i].w, kv[j].w, s[i][j]);
                }
        }

        // Causal mask: only the diagonal block needs it
        if (kb == qb) {
#pragma unroll
            for (int i = 0; i < 4; i++)
#pragma unroll
                for (int j = 0; j < 4; j++)
                    if (cg + 16 * j > rg + 16 * i) s[i][j] = -1e30f;
        }

        // Online softmax update per owned row
#pragma unroll
        for (int i = 0; i < 4; i++) {
            float bmax = fmaxf(fmaxf(s[i][0], s[i][1]), fmaxf(s[i][2], s[i][3]));
            bmax = fmaxf(bmax, __shfl_xor_sync(0xffffffffu, bmax, 1));
            bmax = fmaxf(bmax, __shfl_xor_sync(0xffffffffu, bmax, 2));
            bmax = fmaxf(bmax, __shfl_xor_sync(0xffffffffu, bmax, 4));
            bmax = fmaxf(bmax, __shfl_xor_sync(0xffffffffu, bmax, 8));
            const float nm = fmaxf(m_i[i], bmax);
            const float f = __expf(m_i[i] - nm);
            float ps = 0.0f;
#pragma unroll
            for (int j = 0; j < 4; j++) {
                float p = __expf(s[i][j] - nm);
                Ps[(rg + 16 * i) * 65 + cg + 16 * j] = p;
                ps += p;
            }
            ps += __shfl_xor_sync(0xffffffffu, ps, 1);
            ps += __shfl_xor_sync(0xffffffffu, ps, 2);
            ps += __shfl_xor_sync(0xffffffffu, ps, 4);
            ps += __shfl_xor_sync(0xffffffffu, ps, 8);
            l_i[i] = l_i[i] * f + ps;
            m_i[i] = nm;
#pragma unroll
            for (int j = 0; j < 8; j++) accO[i][j] *= f;
        }
        __syncthreads();  // Ps visible to the whole row group

        // PV: accO[rows rg+16i][cols cg*8..cg*8+7] += P * V
        const int c0 = cg * 8;
#pragma unroll 4
        for (int k = 0; k < 64; k++) {
            float4 v0 = *(const float4*)&Vs[k * 132 + c0];
            float4 v1 = *(const float4*)&Vs[k * 132 + c0 + 4];
#pragma unroll
            for (int i = 0; i < 4; i++) {
                float p = Ps[(rg + 16 * i) * 65 + k];
                accO[i][0] = fmaf(p, v0.x, accO[i][0]);
                accO[i][1] = fmaf(p, v0.y, accO[i][1]);
                accO[i][2] = fmaf(p, v0.z, accO[i][2]);
                accO[i][3] = fmaf(p, v0.w, accO[i][3]);
                accO[i][4] = fmaf(p, v1.x, accO[i][4]);
                accO[i][5] = fmaf(p, v1.y, accO[i][5]);
                accO[i][6] = fmaf(p, v1.z, accO[i][6]);
                accO[i][7] = fmaf(p, v1.w, accO[i][7]);
            }
        }
        __syncthreads();  // before next tile overwrites Ks/Vs
    }

    // Normalize + write O in [B,S,D]
    const int b = bh >> 4;
    const int h = bh & 15;
#pragma unroll
    for (int i = 0; i < 4; i++) {
        const int srow = q0 + rg + 16 * i;
        const float inv = 1.0f / l_i[i];
        float* op = O + ((size_t)b * Sc + srow) * Dc + h * HDc + cg * 8;
        *(float4*)(op) = make_float4(accO[i][0] * inv, accO[i][1] * inv,
                                     accO[i][2] * inv, accO[i][3] * inv);
        *(float4*)(op + 4) = make_float4(accO[i][4] * inv, accO[i][5] * inv,
                                         accO[i][6] * inv, accO[i][7] * inv);
    }
}

// ---------------------------------------------------------------------------
extern "C" void kernel_launch(void* const* d_in, const int* in_sizes, int n_in,
                              void* d_out, int out_size)
{
    const float* x  = (const float*)d_in[0];
    const float* wq = (const float*)d_in[1];
    const float* wk = (const float*)d_in[2];
    const float* wv = (const float*)d_in[3];
    const float* wo = (const float*)d_in[4];
    const int* pos  = (const int*)d_in[5];

    float *q, *k, *v, *o;
    cudaGetSymbolAddress((void**)&q, g_Q);
    cudaGetSymbolAddress((void**)&k, g_K);
    cudaGetSymbolAddress((void**)&v, g_V);
    cudaGetSymbolAddress((void**)&o, g_O);

    dim3 gg(Dc / 128, Mc / 128);  // (16, 64)
    gemm_nt<2><<<gg, 256>>>(x, wq, q, pos);   // Q proj + RoPE -> [B,H,S,HD]
    gemm_nt<2><<<gg, 256>>>(x, wk, k, pos);   // K proj + RoPE -> [B,H,S,HD]
    gemm_nt<1><<<gg, 256>>>(x, wv, v, pos);   // V proj        -> [B,H,S,HD]

    const size_t smem = (size_t)(3 * 64 * 132 + 64 * 65) * sizeof(float);
    cudaFuncSetAttribute(attn_kernel,
                         cudaFuncAttributeMaxDynamicSharedMemorySize, (int)smem);
    attn_kernel<<<dim3(Sc / 64, Bc * Hc), 256, smem>>>(q, k, v, o);

    gemm_nt<0><<<gg, 256>>>(o, wo, (float*)d_out, pos);  // output proj
}

// round 2
// speedup vs baseline: 1.9756x; 1.9756x over previous
#include <cuda_runtime.h>
#include <math.h>
#include <stdint.h>

// Problem dims
constexpr int Bc = 4, Sc = 2048, Dc = 2048, Hc = 16, HDc = 128;
constexpr int Mc = Bc * Sc;  // 8192 rows for all GEMMs

// Scratch (module-static device memory: allowed; no runtime allocation)
__device__ float g_Q[Bc * Hc * Sc * HDc];  // [B,H,S,HD]
__device__ float g_K[Bc * Hc * Sc * HDc];  // [B,H,S,HD]
__device__ float g_V[Bc * Hc * Sc * HDc];  // [B,H,S,HD]
__device__ float g_O[Bc * Sc * Dc];        // [B,S,D]

// ---------------------------------------------------------------------------
// tf32 helpers
// ---------------------------------------------------------------------------
__device__ __forceinline__ float tf32_rn(float x) {
    uint32_t u;
    asm("cvt.rna.tf32.f32 %0, %1;" : "=r"(u) : "f"(x));
    return __uint_as_float(u);
}

__device__ __forceinline__ void mma_tf32(float* d, const uint32_t* a, const uint32_t* b) {
    asm volatile(
        "mma.sync.aligned.m16n8k8.row.col.f32.tf32.tf32.f32 "
        "{%0,%1,%2,%3},{%4,%5,%6,%7},{%8,%9},{%0,%1,%2,%3};"
        : "+f"(d[0]), "+f"(d[1]), "+f"(d[2]), "+f"(d[3])
        : "r"(a[0]), "r"(a[1]), "r"(a[2]), "r"(a[3]), "r"(b[0]), "r"(b[1]));
}

// ---------------------------------------------------------------------------
// GEMM: C[M,N] = A[M,K] * W[N,K]^T  via tf32 mma.sync (fp32 accumulate)
// MODE 0: row-major output [M,N]
// MODE 1: output scattered to [B,H,S,HD]
// MODE 2: MODE 1 + fused RoPE
// CTA tile 128x128x32; 8 warps, warp tile 64x32 (4x4 m16n8k8 tiles).
// smem stride 36 floats: fragment reads conflict-free (bank = 4g + t4).
// ---------------------------------------------------------------------------
template <int MODE>
__global__ void __launch_bounds__(256, 2)
gemm_tf32(const float* __restrict__ A, const float* __restrict__ W,
          float* __restrict__ out, const int* __restrict__ pos)
{
    constexpr int Kd = Dc;
    constexpr int Nd = Dc;
    constexpr int LDS = 36;
    __shared__ float As[128 * LDS];
    __shared__ float Bs[128 * LDS];

    const int tid  = threadIdx.x;
    const int bm   = blockIdx.y * 128;
    const int bn   = blockIdx.x * 128;
    const int wid  = tid >> 5;
    const int lane = tid & 31;
    const int wm   = (wid >> 2) * 64;   // warp row offset: 0 / 64
    const int wn   = (wid & 3) * 32;    // warp col offset: 0/32/64/96
    const int g    = lane >> 2;         // group id 0..7
    const int t4   = lane & 3;          // thread-in-group 0..3

    // Global load assignment: thread covers rows {lr, lr+32, lr+64, lr+96},
    // 4 consecutive floats at column offset lc within the 32-wide k-tile.
    const int lr = tid >> 3;            // 0..31
    const int lc = (tid & 7) * 4;       // 0..28
    const float* Ag = A + (size_t)(bm + lr) * Kd + lc;
    const float* Wg = W + (size_t)(bn + lr) * Kd + lc;

    float acc[4][4][4];
#pragma unroll
    for (int mt = 0; mt < 4; mt++)
#pragma unroll
        for (int nt = 0; nt < 4; nt++)
#pragma unroll
            for (int r = 0; r < 4; r++) acc[mt][nt][r] = 0.0f;

    float4 pa[4], pb[4];
#pragma unroll
    for (int p = 0; p < 4; p++) {
        pa[p] = *(const float4*)(Ag + (size_t)p * 32 * Kd);
        pb[p] = *(const float4*)(Wg + (size_t)p * 32 * Kd);
    }

    for (int kt = 0; kt < Kd; kt += 32) {
        // Store prefetched tile to smem with tf32 round-to-nearest
#pragma unroll
        for (int p = 0; p < 4; p++) {
            float* as = &As[(lr + p * 32) * LDS + lc];
            as[0] = tf32_rn(pa[p].x); as[1] = tf32_rn(pa[p].y);
            as[2] = tf32_rn(pa[p].z); as[3] = tf32_rn(pa[p].w);
            float* bs = &Bs[(lr + p * 32) * LDS + lc];
            bs[0] = tf32_rn(pb[p].x); bs[1] = tf32_rn(pb[p].y);
            bs[2] = tf32_rn(pb[p].z); bs[3] = tf32_rn(pb[p].w);
        }
        __syncthreads();

        // Prefetch next k-tile (overlaps with MMA phase)
        if (kt + 32 < Kd) {
#pragma unroll
            for (int p = 0; p < 4; p++) {
                pa[p] = *(const float4*)(Ag + (size_t)p * 32 * Kd + kt + 32);
                pb[p] = *(const float4*)(Wg + (size_t)p * 32 * Kd + kt + 32);
            }
        }

#pragma unroll
        for (int ks = 0; ks < 4; ks++) {
            const int k0 = ks * 8;
            uint32_t af[4][4], bf[4][2];
#pragma unroll
            for (int mt = 0; mt < 4; mt++) {
                const int r0 = (wm + mt * 16 + g) * LDS + k0 + t4;
                af[mt][0] = __float_as_uint(As[r0]);
                af[mt][1] = __float_as_uint(As[r0 + 8 * LDS]);
                af[mt][2] = __float_as_uint(As[r0 + 4]);
                af[mt][3] = __float_as_uint(As[r0 + 8 * LDS + 4]);
            }
#pragma unroll
            for (int nt = 0; nt < 4; nt++) {
                const int c0 = (wn + nt * 8 + g) * LDS + k0 + t4;
                bf[nt][0] = __float_as_uint(Bs[c0]);
                bf[nt][1] = __float_as_uint(Bs[c0 + 4]);
            }
#pragma unroll
            for (int mt = 0; mt < 4; mt++)
#pragma unroll
                for (int nt = 0; nt < 4; nt++)
                    mma_tf32(acc[mt][nt], af[mt], bf[nt]);
        }
        __syncthreads();
    }

    // Epilogue. Accumulator: thread holds rows (g, g+8), cols (2*t4, 2*t4+1)
    // per 16x8 tile — the col pair is exactly a RoPE rotation pair.
#pragma unroll
    for (int nt = 0; nt < 4; nt++) {
        const int col = bn + wn + nt * 8 + 2 * t4;   // even
        if (MODE == 0) {
#pragma unroll
            for (int mt = 0; mt < 4; mt++) {
                const int r0 = bm + wm + mt * 16 + g;
                *(float2*)&out[(size_t)r0 * Nd + col] =
                    make_float2(acc[mt][nt][0], acc[mt][nt][1]);
                *(float2*)&out[(size_t)(r0 + 8) * Nd + col] =
                    make_float2(acc[mt][nt][2], acc[mt][nt][3]);
            }
        } else {
            const int h  = col >> 7;
            const int hd = col & 127;
            float invf = 0.0f;
            if (MODE == 2)
                invf = (float)exp2(-(double)hd * (13.287712379549449 / 128.0));
#pragma unroll
            for (int mt = 0; mt < 4; mt++) {
#pragma unroll
                for (int rr = 0; rr < 2; rr++) {
                    const int m = bm + wm + mt * 16 + g + rr * 8;
                    const int b = m >> 11;
                    const int s = m & 2047;
                    float x1 = acc[mt][nt][rr * 2];
                    float x2 = acc[mt][nt][rr * 2 + 1];
                    float r1 = x1, r2 = x2;
                    if (MODE == 2) {
                        const float ang = (float)pos[s] * invf;
                        float sn, cs;
                        sincosf(ang, &sn, &cs);
                        r1 = x1 * cs - x2 * sn;
                        r2 = x1 * sn + x2 * cs;
                    }
                    *(float2*)&out[(((size_t)b * Hc + h) * Sc + s) * HDc + hd] =
                        make_float2(r1, r2);
                }
            }
        }
    }
}

// ---------------------------------------------------------------------------
// Flash attention (causal), fp32 SIMT — unchanged from round 1.
// ---------------------------------------------------------------------------
__global__ void __launch_bounds__(256, 1)
attn_kernel(const float* __restrict__ Q, const float* __restrict__ K,
            const float* __restrict__ V, float* __restrict__ O)
{
    extern __shared__ float sm[];
    float* Qs = sm;                    // 64 x 132
    float* Ks = Qs + 64 * 132;         // 64 x 132
    float* Vs = Ks + 64 * 132;         // 64 x 132
    float* Ps = Vs + 64 * 132;         // 64 x 65

    const int tid = threadIdx.x;
    const int qb = blockIdx.x;
    const int bh = blockIdx.y;
    const int q0 = qb * 64;
    const size_t hoff = (size_t)bh * Sc * HDc;
    const float scale = 0.08838834764831845f;  // 1/sqrt(128)

    const float* Qg = Q + hoff + (size_t)q0 * HDc;
    for (int i = tid; i < 64 * 32; i += 256) {
        int r = i >> 5, c = (i & 31) * 4;
        float4 v = *(const float4*)(Qg + (size_t)r * HDc + c);
        v.x *= scale; v.y *= scale; v.z *= scale; v.w *= scale;
        *(float4*)&Qs[r * 132 + c] = v;
    }

    const int rg = tid >> 4;
    const int cg = tid & 15;
    float m_i[4], l_i[4], accO[4][8];
#pragma unroll
    for (int i = 0; i < 4; i++) {
        m_i[i] = -1e30f;
        l_i[i] = 0.0f;
#pragma unroll
        for (int j = 0; j < 8; j++) accO[i][j] = 0.0f;
    }
    __syncthreads();

    for (int kb = 0; kb <= qb; kb++) {
        const float* Kg = K + hoff + (size_t)kb * 64 * HDc;
        const float* Vg = V + hoff + (size_t)kb * 64 * HDc;
        for (int i = tid; i < 64 * 32; i += 256) {
            int r = i >> 5, c = (i & 31) * 4;
            *(float4*)&Ks[r * 132 + c] = *(const float4*)(Kg + (size_t)r * HDc + c);
            *(float4*)&Vs[r * 132 + c] = *(const float4*)(Vg + (size_t)r * HDc + c);
        }
        __syncthreads();

        float s[4][4];
#pragma unroll
        for (int i = 0; i < 4; i++)
#pragma unroll
            for (int j = 0; j < 4; j++) s[i][j] = 0.0f;

        for (int d = 0; d < 128; d += 4) {
            float4 qv[4], kv[4];
#pragma unroll
            for (int i = 0; i < 4; i++)
                qv[i] = *(const float4*)&Qs[(rg + 16 * i) * 132 + d];
#pragma unroll
            for (int j = 0; j < 4; j++)
                kv[j] = *(const float4*)&Ks[(cg + 16 * j) * 132 + d];
#pragma unroll
            for (int i = 0; i < 4; i++)
#pragma unroll
                for (int j = 0; j < 4; j++) {
                    s[i][j] = fmaf(qv[i].x, kv[j].x, s[i][j]);
                    s[i][j] = fmaf(qv[i].y, kv[j].y, s[i][j]);
                    s[i][j] = fmaf(qv[i].z, kv[j].z, s[i][j]);
                    s[i][j] = fmaf(qv[i].w, kv[j].w, s[i][j]);
                }
        }

        if (kb == qb) {
#pragma unroll
            for (int i = 0; i < 4; i++)
#pragma unroll
                for (int j = 0; j < 4; j++)
                    if (cg + 16 * j > rg + 16 * i) s[i][j] = -1e30f;
        }

#pragma unroll
        for (int i = 0; i < 4; i++) {
            float bmax = fmaxf(fmaxf(s[i][0], s[i][1]), fmaxf(s[i][2], s[i][3]));
            bmax = fmaxf(bmax, __shfl_xor_sync(0xffffffffu, bmax, 1));
            bmax = fmaxf(bmax, __shfl_xor_sync(0xffffffffu, bmax, 2));
            bmax = fmaxf(bmax, __shfl_xor_sync(0xffffffffu, bmax, 4));
            bmax = fmaxf(bmax, __shfl_xor_sync(0xffffffffu, bmax, 8));
            const float nm = fmaxf(m_i[i], bmax);
            const float f = __expf(m_i[i] - nm);
            float ps = 0.0f;
#pragma unroll
            for (int j = 0; j < 4; j++) {
                float p = __expf(s[i][j] - nm);
                Ps[(rg + 16 * i) * 65 + cg + 16 * j] = p;
                ps += p;
            }
            ps += __shfl_xor_sync(0xffffffffu, ps, 1);
            ps += __shfl_xor_sync(0xffffffffu, ps, 2);
            ps += __shfl_xor_sync(0xffffffffu, ps, 4);
            ps += __shfl_xor_sync(0xffffffffu, ps, 8);
            l_i[i] = l_i[i] * f + ps;
            m_i[i] = nm;
#pragma unroll
            for (int j = 0; j < 8; j++) accO[i][j] *= f;
        }
        __syncthreads();

        const int c0 = cg * 8;
#pragma unroll 4
        for (int k = 0; k < 64; k++) {
            float4 v0 = *(const float4*)&Vs[k * 132 + c0];
            float4 v1 = *(const float4*)&Vs[k * 132 + c0 + 4];
#pragma unroll
            for (int i = 0; i < 4; i++) {
                float p = Ps[(rg + 16 * i) * 65 + k];
                accO[i][0] = fmaf(p, v0.x, accO[i][0]);
                accO[i][1] = fmaf(p, v0.y, accO[i][1]);
                accO[i][2] = fmaf(p, v0.z, accO[i][2]);
                accO[i][3] = fmaf(p, v0.w, accO[i][3]);
                accO[i][4] = fmaf(p, v1.x, accO[i][4]);
                accO[i][5] = fmaf(p, v1.y, accO[i][5]);
                accO[i][6] = fmaf(p, v1.z, accO[i][6]);
                accO[i][7] = fmaf(p, v1.w, accO[i][7]);
            }
        }
        __syncthreads();
    }

    const int b = bh >> 4;
    const int h = bh & 15;
#pragma unroll
    for (int i = 0; i < 4; i++) {
        const int srow = q0 + rg + 16 * i;
        const float inv = 1.0f / l_i[i];
        float* op = O + ((size_t)b * Sc + srow) * Dc + h * HDc + cg * 8;
        *(float4*)(op) = make_float4(accO[i][0] * inv, accO[i][1] * inv,
                                     accO[i][2] * inv, accO[i][3] * inv);
        *(float4*)(op + 4) = make_float4(accO[i][4] * inv, accO[i][5] * inv,
                                         accO[i][6] * inv, accO[i][7] * inv);
    }
}

// ---------------------------------------------------------------------------
extern "C" void kernel_launch(void* const* d_in, const int* in_sizes, int n_in,
                              void* d_out, int out_size)
{
    const float* x  = (const float*)d_in[0];
    const float* wq = (const float*)d_in[1];
    const float* wk = (const float*)d_in[2];
    const float* wv = (const float*)d_in[3];
    const float* wo = (const float*)d_in[4];
    const int* pos  = (const int*)d_in[5];

    float *q, *k, *v, *o;
    cudaGetSymbolAddress((void**)&q, g_Q);
    cudaGetSymbolAddress((void**)&k, g_K);
    cudaGetSymbolAddress((void**)&v, g_V);
    cudaGetSymbolAddress((void**)&o, g_O);

    dim3 gg(Dc / 128, Mc / 128);  // (16, 64)
    gemm_tf32<2><<<gg, 256>>>(x, wq, q, pos);   // Q proj + RoPE -> [B,H,S,HD]
    gemm_tf32<2><<<gg, 256>>>(x, wk, k, pos);   // K proj + RoPE -> [B,H,S,HD]
    gemm_tf32<1><<<gg, 256>>>(x, wv, v, pos);   // V proj        -> [B,H,S,HD]

    const size_t smem = (size_t)(3 * 64 * 132 + 64 * 65) * sizeof(float);
    cudaFuncSetAttribute(attn_kernel,
                         cudaFuncAttributeMaxDynamicSharedMemorySize, (int)smem);
    attn_kernel<<<dim3(Sc / 64, Bc * Hc), 256, smem>>>(q, k, v, o);

    gemm_tf32<0><<<gg, 256>>>(o, wo, (float*)d_out, pos);  // output proj
}

// round 3
// speedup vs baseline: 3.4392x; 1.7408x over previous
#include <cuda_runtime.h>
#include <math.h>
#include <stdint.h>

// Problem dims
constexpr int Bc = 4, Sc = 2048, Dc = 2048, Hc = 16, HDc = 128;
constexpr int Mc = Bc * Sc;  // 8192 rows for all GEMMs

// Scratch (module-static device memory: allowed; no runtime allocation)
__device__ float g_Q[Bc * Hc * Sc * HDc];  // [B,H,S,HD]
__device__ float g_K[Bc * Hc * Sc * HDc];  // [B,H,S,HD]
__device__ float g_V[Bc * Hc * Sc * HDc];  // [B,H,S,HD]
__device__ float g_O[Bc * Sc * Dc];        // [B,S,D]

// ---------------------------------------------------------------------------
// tf32 helpers
// ---------------------------------------------------------------------------
__device__ __forceinline__ float tf32_rn(float x) {
    uint32_t u;
    asm("cvt.rna.tf32.f32 %0, %1;" : "=r"(u) : "f"(x));
    return __uint_as_float(u);
}

__device__ __forceinline__ void mma_tf32(float* d, const uint32_t* a, const uint32_t* b) {
    asm volatile(
        "mma.sync.aligned.m16n8k8.row.col.f32.tf32.tf32.f32 "
        "{%0,%1,%2,%3},{%4,%5,%6,%7},{%8,%9},{%0,%1,%2,%3};"
        : "+f"(d[0]), "+f"(d[1]), "+f"(d[2]), "+f"(d[3])
        : "r"(a[0]), "r"(a[1]), "r"(a[2]), "r"(a[3]), "r"(b[0]), "r"(b[1]));
}

// ---------------------------------------------------------------------------
// GEMM: C[M,N] = A[M,K] * W[N,K]^T  via tf32 mma.sync (fp32 accumulate)
// MODE 0: row-major output [M,N]
// MODE 1: output scattered to [B,H,S,HD]
// MODE 2: MODE 1 + fused RoPE
// ---------------------------------------------------------------------------
template <int MODE>
__global__ void __launch_bounds__(256, 2)
gemm_tf32(const float* __restrict__ A, const float* __restrict__ W,
          float* __restrict__ out, const int* __restrict__ pos)
{
    constexpr int Kd = Dc;
    constexpr int Nd = Dc;
    constexpr int LDS = 36;
    __shared__ float As[128 * LDS];
    __shared__ float Bs[128 * LDS];

    const int tid  = threadIdx.x;
    const int bm   = blockIdx.y * 128;
    const int bn   = blockIdx.x * 128;
    const int wid  = tid >> 5;
    const int lane = tid & 31;
    const int wm   = (wid >> 2) * 64;
    const int wn   = (wid & 3) * 32;
    const int g    = lane >> 2;
    const int t4   = lane & 3;

    const int lr = tid >> 3;
    const int lc = (tid & 7) * 4;
    const float* Ag = A + (size_t)(bm + lr) * Kd + lc;
    const float* Wg = W + (size_t)(bn + lr) * Kd + lc;

    float acc[4][4][4];
#pragma unroll
    for (int mt = 0; mt < 4; mt++)
#pragma unroll
        for (int nt = 0; nt < 4; nt++)
#pragma unroll
            for (int r = 0; r < 4; r++) acc[mt][nt][r] = 0.0f;

    float4 pa[4], pb[4];
#pragma unroll
    for (int p = 0; p < 4; p++) {
        pa[p] = *(const float4*)(Ag + (size_t)p * 32 * Kd);
        pb[p] = *(const float4*)(Wg + (size_t)p * 32 * Kd);
    }

    for (int kt = 0; kt < Kd; kt += 32) {
#pragma unroll
        for (int p = 0; p < 4; p++) {
            float* as = &As[(lr + p * 32) * LDS + lc];
            as[0] = tf32_rn(pa[p].x); as[1] = tf32_rn(pa[p].y);
            as[2] = tf32_rn(pa[p].z); as[3] = tf32_rn(pa[p].w);
            float* bs = &Bs[(lr + p * 32) * LDS + lc];
            bs[0] = tf32_rn(pb[p].x); bs[1] = tf32_rn(pb[p].y);
            bs[2] = tf32_rn(pb[p].z); bs[3] = tf32_rn(pb[p].w);
        }
        __syncthreads();

        if (kt + 32 < Kd) {
#pragma unroll
            for (int p = 0; p < 4; p++) {
                pa[p] = *(const float4*)(Ag + (size_t)p * 32 * Kd + kt + 32);
                pb[p] = *(const float4*)(Wg + (size_t)p * 32 * Kd + kt + 32);
            }
        }

#pragma unroll
        for (int ks = 0; ks < 4; ks++) {
            const int k0 = ks * 8;
            uint32_t af[4][4], bf[4][2];
#pragma unroll
            for (int mt = 0; mt < 4; mt++) {
                const int r0 = (wm + mt * 16 + g) * LDS + k0 + t4;
                af[mt][0] = __float_as_uint(As[r0]);
                af[mt][1] = __float_as_uint(As[r0 + 8 * LDS]);
                af[mt][2] = __float_as_uint(As[r0 + 4]);
                af[mt][3] = __float_as_uint(As[r0 + 8 * LDS + 4]);
            }
#pragma unroll
            for (int nt = 0; nt < 4; nt++) {
                const int c0 = (wn + nt * 8 + g) * LDS + k0 + t4;
                bf[nt][0] = __float_as_uint(Bs[c0]);
                bf[nt][1] = __float_as_uint(Bs[c0 + 4]);
            }
#pragma unroll
            for (int mt = 0; mt < 4; mt++)
#pragma unroll
                for (int nt = 0; nt < 4; nt++)
                    mma_tf32(acc[mt][nt], af[mt], bf[nt]);
        }
        __syncthreads();
    }

#pragma unroll
    for (int nt = 0; nt < 4; nt++) {
        const int col = bn + wn + nt * 8 + 2 * t4;
        if (MODE == 0) {
#pragma unroll
            for (int mt = 0; mt < 4; mt++) {
                const int r0 = bm + wm + mt * 16 + g;
                *(float2*)&out[(size_t)r0 * Nd + col] =
                    make_float2(acc[mt][nt][0], acc[mt][nt][1]);
                *(float2*)&out[(size_t)(r0 + 8) * Nd + col] =
                    make_float2(acc[mt][nt][2], acc[mt][nt][3]);
            }
        } else {
            const int h  = col >> 7;
            const int hd = col & 127;
            float invf = 0.0f;
            if (MODE == 2)
                invf = (float)exp2(-(double)hd * (13.287712379549449 / 128.0));
#pragma unroll
            for (int mt = 0; mt < 4; mt++) {
#pragma unroll
                for (int rr = 0; rr < 2; rr++) {
                    const int m = bm + wm + mt * 16 + g + rr * 8;
                    const int b = m >> 11;
                    const int s = m & 2047;
                    float x1 = acc[mt][nt][rr * 2];
                    float x2 = acc[mt][nt][rr * 2 + 1];
                    float r1 = x1, r2 = x2;
                    if (MODE == 2) {
                        const float ang = (float)pos[s] * invf;
                        float sn, cs;
                        sincosf(ang, &sn, &cs);
                        r1 = x1 * cs - x2 * sn;
                        r2 = x1 * sn + x2 * cs;
                    }
                    *(float2*)&out[(((size_t)b * Hc + h) * Sc + s) * HDc + hd] =
                        make_float2(r1, r2);
                }
            }
        }
    }
}

// ---------------------------------------------------------------------------
// Flash attention (causal) via tf32 mma.sync.
// CTA: 128 query rows x one (b,h); 8 warps, 16 rows/warp; key tiles of 64.
// Qs/Ks stride 132 (frag bank 4g+t4, clean); Vs stride 136 (bank 8t4+g, clean);
// Ps stride 68 (reads clean, writes 2-way — negligible).
// ---------------------------------------------------------------------------
__global__ void __launch_bounds__(256, 1)
attn_mma(const float* __restrict__ Q, const float* __restrict__ K,
         const float* __restrict__ V, float* __restrict__ O)
{
    extern __shared__ float sm[];
    float* Qs = sm;                  // 128 x 132
    float* Ks = Qs + 128 * 132;      // 64 x 132
    float* Vs = Ks + 64 * 132;       // 64 x 136
    float* Ps = Vs + 64 * 136;       // 128 x 68

    const int tid  = threadIdx.x;
    const int wid  = tid >> 5;
    const int lane = tid & 31;
    const int g    = lane >> 2;
    const int t4   = lane & 3;
    const int qb   = (gridDim.x - 1) - blockIdx.x;   // heavy blocks first
    const int bh   = blockIdx.y;
    const int q0   = qb * 128;
    const size_t hoff = (size_t)bh * (size_t)(Sc * HDc);
    const float scale = 0.08838834764831845f;        // 1/sqrt(128)

    // Load Q tile: scale then tf32-round
    const float* Qg = Q + hoff + (size_t)q0 * HDc;
    for (int i = tid; i < 128 * 32; i += 256) {
        int r = i >> 5, c = (i & 31) * 4;
        float4 v = *(const float4*)(Qg + (size_t)r * HDc + c);
        float* qs = &Qs[r * 132 + c];
        qs[0] = tf32_rn(v.x * scale); qs[1] = tf32_rn(v.y * scale);
        qs[2] = tf32_rn(v.z * scale); qs[3] = tf32_rn(v.w * scale);
    }

    float accO[16][4];
#pragma unroll
    for (int nt = 0; nt < 16; nt++)
#pragma unroll
        for (int r = 0; r < 4; r++) accO[nt][r] = 0.0f;
    float m0 = -1e30f, m1 = -1e30f, l0 = 0.0f, l1 = 0.0f;
    __syncthreads();

    const int rowb = wid * 16;
    const int nkb = 2 * qb + 2;
    for (int kb = 0; kb < nkb; kb++) {
        const float* Kg = K + hoff + (size_t)(kb * 64) * HDc;
        const float* Vg = V + hoff + (size_t)(kb * 64) * HDc;
        for (int i = tid; i < 64 * 32; i += 256) {
            int r = i >> 5, c = (i & 31) * 4;
            float4 kv = *(const float4*)(Kg + (size_t)r * HDc + c);
            float* ks = &Ks[r * 132 + c];
            ks[0] = tf32_rn(kv.x); ks[1] = tf32_rn(kv.y);
            ks[2] = tf32_rn(kv.z); ks[3] = tf32_rn(kv.w);
            float4 vv = *(const float4*)(Vg + (size_t)r * HDc + c);
            float* vs = &Vs[r * 136 + c];
            vs[0] = tf32_rn(vv.x); vs[1] = tf32_rn(vv.y);
            vs[2] = tf32_rn(vv.z); vs[3] = tf32_rn(vv.w);
        }
        __syncthreads();

        // Scores: warp rows [rowb, rowb+16) x 64 keys
        float s[8][4];
#pragma unroll
        for (int nt = 0; nt < 8; nt++)
#pragma unroll
            for (int r = 0; r < 4; r++) s[nt][r] = 0.0f;

#pragma unroll
        for (int ks_ = 0; ks_ < 16; ks_++) {
            const int k0 = ks_ * 8;
            uint32_t a[4];
            const int r0 = (rowb + g) * 132 + k0 + t4;
            a[0] = __float_as_uint(Qs[r0]);
            a[1] = __float_as_uint(Qs[r0 + 8 * 132]);
            a[2] = __float_as_uint(Qs[r0 + 4]);
            a[3] = __float_as_uint(Qs[r0 + 8 * 132 + 4]);
#pragma unroll
            for (int nt = 0; nt < 8; nt++) {
                uint32_t b[2];
                const int c0 = (nt * 8 + g) * 132 + k0 + t4;
                b[0] = __float_as_uint(Ks[c0]);
                b[1] = __float_as_uint(Ks[c0 + 4]);
                mma_tf32(s[nt], a, b);
            }
        }

        // Causal mask (only the two diagonal tiles)
        if (kb >= 2 * qb) {
            const int colb = kb * 64 + 2 * t4;
            const int row0 = q0 + rowb + g;
#pragma unroll
            for (int nt = 0; nt < 8; nt++) {
                const int c0 = colb + nt * 8;
                if (c0     > row0)     s[nt][0] = -1e30f;
                if (c0 + 1 > row0)     s[nt][1] = -1e30f;
                if (c0     > row0 + 8) s[nt][2] = -1e30f;
                if (c0 + 1 > row0 + 8) s[nt][3] = -1e30f;
            }
        }

        // Online softmax on fragments (rows g and g+8)
        float bm0 = -1e30f, bm1 = -1e30f;
#pragma unroll
        for (int nt = 0; nt < 8; nt++) {
            bm0 = fmaxf(bm0, fmaxf(s[nt][0], s[nt][1]));
            bm1 = fmaxf(bm1, fmaxf(s[nt][2], s[nt][3]));
        }
        bm0 = fmaxf(bm0, __shfl_xor_sync(0xffffffffu, bm0, 1));
        bm0 = fmaxf(bm0, __shfl_xor_sync(0xffffffffu, bm0, 2));
        bm1 = fmaxf(bm1, __shfl_xor_sync(0xffffffffu, bm1, 1));
        bm1 = fmaxf(bm1, __shfl_xor_sync(0xffffffffu, bm1, 2));
        const float nm0 = fmaxf(m0, bm0);
        const float nm1 = fmaxf(m1, bm1);
        const float f0 = __expf(m0 - nm0);
        const float f1 = __expf(m1 - nm1);
        float ps0 = 0.0f, ps1 = 0.0f;
#pragma unroll
        for (int nt = 0; nt < 8; nt++) {
            float p0 = tf32_rn(__expf(s[nt][0] - nm0));
            float p1 = tf32_rn(__expf(s[nt][1] - nm0));
            float p2 = tf32_rn(__expf(s[nt][2] - nm1));
            float p3 = tf32_rn(__expf(s[nt][3] - nm1));
            ps0 += p0 + p1;
            ps1 += p2 + p3;
            const int cc = nt * 8 + 2 * t4;
            *(float2*)&Ps[(rowb + g) * 68 + cc]     = make_float2(p0, p1);
            *(float2*)&Ps[(rowb + g + 8) * 68 + cc] = make_float2(p2, p3);
        }
        ps0 += __shfl_xor_sync(0xffffffffu, ps0, 1);
        ps0 += __shfl_xor_sync(0xffffffffu, ps0, 2);
        ps1 += __shfl_xor_sync(0xffffffffu, ps1, 1);
        ps1 += __shfl_xor_sync(0xffffffffu, ps1, 2);
        l0 = l0 * f0 + ps0;
        l1 = l1 * f1 + ps1;
        m0 = nm0;
        m1 = nm1;
#pragma unroll
        for (int nt = 0; nt < 16; nt++) {
            accO[nt][0] *= f0; accO[nt][1] *= f0;
            accO[nt][2] *= f1; accO[nt][3] *= f1;
        }
        __syncwarp();  // Ps rows are warp-private; make writes visible

        // PV: accO += P[16x64] * V[64x128]
#pragma unroll
        for (int ks_ = 0; ks_ < 8; ks_++) {
            const int k0 = ks_ * 8;
            uint32_t a[4];
            const int r0 = (rowb + g) * 68 + k0 + t4;
            a[0] = __float_as_uint(Ps[r0]);
            a[1] = __float_as_uint(Ps[r0 + 8 * 68]);
            a[2] = __float_as_uint(Ps[r0 + 4]);
            a[3] = __float_as_uint(Ps[r0 + 8 * 68 + 4]);
#pragma unroll
            for (int nt = 0; nt < 16; nt++) {
                uint32_t b[2];
                const int c0 = (k0 + t4) * 136 + nt * 8 + g;
                b[0] = __float_as_uint(Vs[c0]);
                b[1] = __float_as_uint(Vs[c0 + 4 * 136]);
                mma_tf32(accO[nt], a, b);
            }
        }
        __syncthreads();  // before next tile overwrites Ks/Vs
    }

    // Normalize + write O in [B,S,D]
    const int b_ = bh >> 4;
    const int h_ = bh & 15;
    const float inv0 = 1.0f / l0;
    const float inv1 = 1.0f / l1;
    const int r0g = q0 + rowb + g;
    float* Op0 = O + ((size_t)b_ * Sc + r0g) * Dc + h_ * HDc;
    float* Op1 = Op0 + (size_t)8 * Dc;
#pragma unroll
    for (int nt = 0; nt < 16; nt++) {
        const int cc = nt * 8 + 2 * t4;
        *(float2*)&Op0[cc] = make_float2(accO[nt][0] * inv0, accO[nt][1] * inv0);
        *(float2*)&Op1[cc] = make_float2(accO[nt][2] * inv1, accO[nt][3] * inv1);
    }
}

// ---------------------------------------------------------------------------
extern "C" void kernel_launch(void* const* d_in, const int* in_sizes, int n_in,
                              void* d_out, int out_size)
{
    const float* x  = (const float*)d_in[0];
    const float* wq = (const float*)d_in[1];
    const float* wk = (const float*)d_in[2];
    const float* wv = (const float*)d_in[3];
    const float* wo = (const float*)d_in[4];
    const int* pos  = (const int*)d_in[5];

    float *q, *k, *v, *o;
    cudaGetSymbolAddress((void**)&q, g_Q);
    cudaGetSymbolAddress((void**)&k, g_K);
    cudaGetSymbolAddress((void**)&v, g_V);
    cudaGetSymbolAddress((void**)&o, g_O);

    dim3 gg(Dc / 128, Mc / 128);  // (16, 64)
    gemm_tf32<2><<<gg, 256>>>(x, wq, q, pos);   // Q proj + RoPE -> [B,H,S,HD]
    gemm_tf32<2><<<gg, 256>>>(x, wk, k, pos);   // K proj + RoPE -> [B,H,S,HD]
    gemm_tf32<1><<<gg, 256>>>(x, wv, v, pos);   // V proj        -> [B,H,S,HD]

    const size_t smem = (size_t)(128 * 132 + 64 * 132 + 64 * 136 + 128 * 68) * sizeof(float);
    cudaFuncSetAttribute(attn_mma,
                         cudaFuncAttributeMaxDynamicSharedMemorySize, (int)smem);
    attn_mma<<<dim3(Sc / 128, Bc * Hc), 256, smem>>>(q, k, v, o);

    gemm_tf32<0><<<gg, 256>>>(o, wo, (float*)d_out, pos);  // output proj
}